// round 7
// baseline (speedup 1.0000x reference)
#include <cuda_runtime.h>
#include <cuda_bf16.h>
#include <cstdint>
#include <cstddef>
#include <math.h>

// Problem constants
#define S_DIM 128
#define L_DIM 512
#define D_DIM 256
#define H_DIM 8
#define C_DIM 32
#define HC    256
#define ROWS  65536

// ---------------- scratch (device globals; allocation-free) ----------------
__device__ float g_x[(size_t)ROWS * D_DIM];
__device__ float g_q[(size_t)ROWS * HC];
__device__ float g_k[(size_t)ROWS * HC];
__device__ float g_v[(size_t)ROWS * HC];
__device__ float g_gate[(size_t)ROWS * HC];
__device__ float g_o[(size_t)ROWS * HC];
__device__ float g_wT[5 * 256 * 256];   // weights transposed to [n][k]; slots: wq,wk,wv,wg,wo

__device__ __forceinline__ uint32_t f2tf(float f) {
    uint32_t u;
    asm("cvt.rna.tf32.f32 %0, %1;" : "=r"(u) : "f"(f));
    return u;
}
__device__ __forceinline__ uint32_t smem_u32(const void* p) {
    uint32_t a;
    asm("{ .reg .u64 t; cvta.to.shared.u64 t, %1; cvt.u32.u64 %0, t; }" : "=r"(a) : "l"(p));
    return a;
}
__device__ __forceinline__ void ldsm4(uint32_t& r0, uint32_t& r1, uint32_t& r2, uint32_t& r3,
                                      uint32_t addr) {
    asm volatile("ldmatrix.sync.aligned.m8n8.x4.shared.b16 {%0,%1,%2,%3}, [%4];"
                 : "=r"(r0), "=r"(r1), "=r"(r2), "=r"(r3) : "r"(addr));
}

// ---------------- LayerNorm: one warp per row of 256 ----------------
__global__ void __launch_bounds__(256) ln_kernel(const float* __restrict__ in,
                                                 const float* __restrict__ sc,
                                                 const float* __restrict__ bi) {
    int row  = blockIdx.x * blockDim.y + threadIdx.y;
    int lane = threadIdx.x;
    const float4* p = (const float4*)(in + (size_t)row * D_DIM);
    float4 a = p[lane];
    float4 b = p[lane + 32];
    float s  = a.x + a.y + a.z + a.w + b.x + b.y + b.z + b.w;
    float s2 = a.x*a.x + a.y*a.y + a.z*a.z + a.w*a.w
             + b.x*b.x + b.y*b.y + b.z*b.z + b.w*b.w;
    #pragma unroll
    for (int off = 16; off > 0; off >>= 1) {
        s  += __shfl_xor_sync(0xFFFFFFFF, s,  off);
        s2 += __shfl_xor_sync(0xFFFFFFFF, s2, off);
    }
    float mean = s * (1.0f / 256.0f);
    float var  = s2 * (1.0f / 256.0f) - mean * mean;
    float inv  = rsqrtf(var + 1e-5f);

    const float4* scp = (const float4*)sc;
    const float4* bip = (const float4*)bi;
    float4 sa = scp[lane], sb = scp[lane + 32];
    float4 ba = bip[lane], bb = bip[lane + 32];
    float4 oa, ob;
    oa.x = (a.x - mean) * inv * sa.x + ba.x;
    oa.y = (a.y - mean) * inv * sa.y + ba.y;
    oa.z = (a.z - mean) * inv * sa.z + ba.z;
    oa.w = (a.w - mean) * inv * sa.w + ba.w;
    ob.x = (b.x - mean) * inv * sb.x + bb.x;
    ob.y = (b.y - mean) * inv * sb.y + bb.y;
    ob.z = (b.z - mean) * inv * sb.z + bb.z;
    ob.w = (b.w - mean) * inv * sb.w + bb.w;
    float4* q = (float4*)(g_x + (size_t)row * D_DIM);
    q[lane]      = oa;
    q[lane + 32] = ob;
}

// ---------------- weight transpose: g_wT[z][n][k] = W_z[k][n] ----------------
__global__ void __launch_bounds__(256) transpose_w(const float* __restrict__ wq,
                                                   const float* __restrict__ wk,
                                                   const float* __restrict__ wv,
                                                   const float* __restrict__ wg,
                                                   const float* __restrict__ wo) {
    const float* srcs[5] = {wq, wk, wv, wg, wo};
    const float* src = srcs[blockIdx.z];
    float* dst = g_wT + (size_t)blockIdx.z * 65536;
    __shared__ float t[32][33];
    int tx = threadIdx.x, ty = threadIdx.y;
    int x  = blockIdx.x * 32 + tx;
    int y0 = blockIdx.y * 32;
    #pragma unroll
    for (int j = 0; j < 32; j += 8)
        t[ty + j][tx] = src[(size_t)(y0 + ty + j) * 256 + x];
    __syncthreads();
    int nx = blockIdx.y * 32 + tx;
    #pragma unroll
    for (int j = 0; j < 32; j += 8)
        dst[(size_t)(blockIdx.x * 32 + ty + j) * 256 + nx] = t[tx][ty + j];
}

// ---------------- TF32 GEMM: 128x128 tile, K=256, ldmatrix fragments ----------------
// A: rows x 256 row-major (k-major). B: [n][k] k-major (pre-transposed weights).
// smem: As/Bs stored [tile_row][BK=16 + pad4] words; row stride 20 words (80B) ->
// 8 consecutive rows hit 8 distinct bank quads (conflict-free LDSM).
#define BKW 20

__device__ __forceinline__ void gemm_ldsm_tile(const float* __restrict__ A,
                                               const float* __restrict__ Bt,
                                               int row0, int col0,
                                               float* __restrict__ Cout, int ldc,
                                               const float* __restrict__ bias,
                                               bool do_sig) {
    __shared__ uint32_t As[128 * BKW];
    __shared__ uint32_t Bs[128 * BKW];

    int tid  = threadIdx.x;
    int lane = tid & 31;
    int wid  = tid >> 5;
    int wm   = wid & 1;
    int wn   = wid >> 1;
    int la3  = lane & 3;
    int lr   = lane >> 2;

    uint32_t sA = smem_u32(As);
    uint32_t sB = smem_u32(Bs);

    // per-lane LDSM base addresses (mi=0 / j=0, kk=0)
    int tileid = lane >> 3;
    int lrow   = lane & 7;
    uint32_t aAddr = sA + (((uint32_t)(wm * 64 + (tileid & 1) * 8 + lrow)) * BKW
                           + (uint32_t)(tileid >> 1) * 4) * 4;
    uint32_t bAddr = sB + (((uint32_t)(wn * 64 + (tileid & 1) * 8 + lrow)) * BKW
                           + (uint32_t)(tileid >> 1) * 4) * 4;

    float acc[4][8][4];
    #pragma unroll
    for (int mi = 0; mi < 4; mi++)
        #pragma unroll
        for (int ni = 0; ni < 8; ni++)
            #pragma unroll
            for (int q = 0; q < 4; q++) acc[mi][ni][q] = 0.0f;

    const float* aRow = A + (size_t)(row0 + tid) * 256;
    const float* bRow = Bt + (size_t)(col0 + tid) * 256;

    float4 pa[4], pb[4];
    #pragma unroll
    for (int q = 0; q < 4; q++) {
        pa[q] = *(const float4*)(aRow + q * 4);
        pb[q] = *(const float4*)(bRow + q * 4);
    }

    for (int c = 0; c < 16; c++) {
        // stage chunk c (regs -> smem, 16B stores, 16B-aligned rows of 80B stride)
        #pragma unroll
        for (int q = 0; q < 4; q++) {
            uint4 ua, ub;
            ua.x = f2tf(pa[q].x); ua.y = f2tf(pa[q].y); ua.z = f2tf(pa[q].z); ua.w = f2tf(pa[q].w);
            ub.x = f2tf(pb[q].x); ub.y = f2tf(pb[q].y); ub.z = f2tf(pb[q].z); ub.w = f2tf(pb[q].w);
            *(uint4*)&As[tid * BKW + q * 4] = ua;
            *(uint4*)&Bs[tid * BKW + q * 4] = ub;
        }
        __syncthreads();

        if (c < 15) {
            #pragma unroll
            for (int q = 0; q < 4; q++) {
                pa[q] = *(const float4*)(aRow + (c + 1) * 16 + q * 4);
                pb[q] = *(const float4*)(bRow + (c + 1) * 16 + q * 4);
            }
        }

        #pragma unroll
        for (int kk = 0; kk < 16; kk += 8) {
            uint32_t af[4][4];
            #pragma unroll
            for (int mi = 0; mi < 4; mi++)
                ldsm4(af[mi][0], af[mi][1], af[mi][2], af[mi][3],
                      aAddr + (uint32_t)(mi * 16 * BKW + kk) * 4);
            uint32_t bf[8][2];
            #pragma unroll
            for (int j = 0; j < 4; j++) {
                uint32_t r0, r1, r2, r3;
                ldsm4(r0, r1, r2, r3, bAddr + (uint32_t)(j * 16 * BKW + kk) * 4);
                bf[2 * j + 0][0] = r0; bf[2 * j + 1][0] = r1;
                bf[2 * j + 0][1] = r2; bf[2 * j + 1][1] = r3;
            }
            #pragma unroll
            for (int mi = 0; mi < 4; mi++)
                #pragma unroll
                for (int ni = 0; ni < 8; ni++) {
                    asm volatile(
                        "mma.sync.aligned.m16n8k8.row.col.f32.tf32.tf32.f32 "
                        "{%0,%1,%2,%3}, {%4,%5,%6,%7}, {%8,%9}, {%0,%1,%2,%3};"
                        : "+f"(acc[mi][ni][0]), "+f"(acc[mi][ni][1]),
                          "+f"(acc[mi][ni][2]), "+f"(acc[mi][ni][3])
                        : "r"(af[mi][0]), "r"(af[mi][1]), "r"(af[mi][2]), "r"(af[mi][3]),
                          "r"(bf[ni][0]), "r"(bf[ni][1]));
                }
        }
        __syncthreads();
    }

    #pragma unroll
    for (int mi = 0; mi < 4; mi++) {
        #pragma unroll
        for (int half = 0; half < 2; half++) {
            int rg = row0 + wm * 64 + mi * 16 + lr + half * 8;
            #pragma unroll
            for (int ni = 0; ni < 8; ni++) {
                int cg = col0 + wn * 64 + ni * 8 + la3 * 2;
                float v0 = acc[mi][ni][half * 2 + 0];
                float v1 = acc[mi][ni][half * 2 + 1];
                if (bias) { v0 += bias[cg]; v1 += bias[cg + 1]; }
                if (do_sig) {
                    v0 = 1.0f / (1.0f + __expf(-v0));
                    v1 = 1.0f / (1.0f + __expf(-v1));
                }
                *(float2*)(Cout + (size_t)rg * ldc + cg) = make_float2(v0, v1);
            }
        }
    }
}

__global__ void __launch_bounds__(128) proj_kernel(const float* __restrict__ bg) {
    int row0 = blockIdx.x * 128;
    int nblk = blockIdx.y;          // 0..7
    int wsel = nblk >> 1;
    int colW = (nblk & 1) * 128;
    const float* Bt = g_wT + (size_t)wsel * 65536;
    float* out;
    const float* bias = nullptr;
    bool sig = false;
    switch (wsel) {
        case 0: out = g_q; break;
        case 1: out = g_k; break;
        case 2: out = g_v; break;
        default: out = g_gate; bias = bg; sig = true; break;
    }
    gemm_ldsm_tile(g_x, Bt, row0, colW, out, HC, bias, sig);
}

__global__ void __launch_bounds__(128) outproj_kernel(const float* __restrict__ bo,
                                                      float* __restrict__ out) {
    int row0 = blockIdx.x * 128;
    int colW = blockIdx.y * 128;
    gemm_ldsm_tile(g_o, g_wT + 4 * 65536, row0, colW, out, D_DIM, bo, false);
}

// ---------------- tensor-core attention per (l, h) (unchanged from R6) ----------------
#define AT_QS 0
#define AT_KS 4224
#define AT_PT 0
#define AT_VS 16896
#define AT_RS 21504
#define ATTN_SMEM ((21504 + 128) * 4)

__global__ void __launch_bounds__(128) attn_tc_kernel() {
    extern __shared__ uint32_t shm[];
    int l = blockIdx.x >> 3;
    int h = blockIdx.x & 7;
    int tid  = threadIdx.x;
    int lane = tid & 31;
    int wid  = tid >> 5;
    int la3  = lane & 3;
    int lr   = lane >> 2;

    const size_t srow = (size_t)L_DIM * HC;
    const size_t base = (size_t)l * HC + (size_t)h * C_DIM;
    const float scale = 0.17677669529663687f;

    {
        int tloc = tid >> 3;
        int cq   = (tid & 7) * 4;
        #pragma unroll
        for (int p = 0; p < 8; p++) {
            int r = p * 16 + tloc;
            size_t gi = base + (size_t)r * srow + cq;
            float4 qv = *(const float4*)(g_q + gi);
            shm[AT_QS + (cq + 0) * 132 + r] = f2tf(qv.x * scale);
            shm[AT_QS + (cq + 1) * 132 + r] = f2tf(qv.y * scale);
            shm[AT_QS + (cq + 2) * 132 + r] = f2tf(qv.z * scale);
            shm[AT_QS + (cq + 3) * 132 + r] = f2tf(qv.w * scale);
            float4 kv = *(const float4*)(g_k + gi);
            shm[AT_KS + (cq + 0) * 132 + r] = f2tf(kv.x);
            shm[AT_KS + (cq + 1) * 132 + r] = f2tf(kv.y);
            shm[AT_KS + (cq + 2) * 132 + r] = f2tf(kv.z);
            shm[AT_KS + (cq + 3) * 132 + r] = f2tf(kv.w);
            float4 vv = *(const float4*)(g_v + gi);
            uint4 u;
            u.x = f2tf(vv.x); u.y = f2tf(vv.y); u.z = f2tf(vv.z); u.w = f2tf(vv.w);
            *(uint4*)&shm[AT_VS + r * 36 + cq] = u;
        }
    }
    __syncthreads();

    float acc1[2][16][4];
    #pragma unroll
    for (int mi = 0; mi < 2; mi++)
        #pragma unroll
        for (int ni = 0; ni < 16; ni++)
            #pragma unroll
            for (int q = 0; q < 4; q++) acc1[mi][ni][q] = 0.0f;

    #pragma unroll
    for (int ks = 0; ks < 4; ks++) {
        int kk = ks * 8;
        uint32_t af[2][4];
        #pragma unroll
        for (int mi = 0; mi < 2; mi++) {
            int r = wid * 32 + mi * 16 + lr;
            af[mi][0] = shm[AT_QS + (kk + la3) * 132 + r];
            af[mi][1] = shm[AT_QS + (kk + la3) * 132 + r + 8];
            af[mi][2] = shm[AT_QS + (kk + 4 + la3) * 132 + r];
            af[mi][3] = shm[AT_QS + (kk + 4 + la3) * 132 + r + 8];
        }
        #pragma unroll
        for (int ni = 0; ni < 16; ni++) {
            uint32_t b0 = shm[AT_KS + (kk + la3) * 132 + ni * 8 + lr];
            uint32_t b1 = shm[AT_KS + (kk + 4 + la3) * 132 + ni * 8 + lr];
            #pragma unroll
            for (int mi = 0; mi < 2; mi++) {
                asm volatile(
                    "mma.sync.aligned.m16n8k8.row.col.f32.tf32.tf32.f32 "
                    "{%0,%1,%2,%3}, {%4,%5,%6,%7}, {%8,%9}, {%0,%1,%2,%3};"
                    : "+f"(acc1[mi][ni][0]), "+f"(acc1[mi][ni][1]),
                      "+f"(acc1[mi][ni][2]), "+f"(acc1[mi][ni][3])
                    : "r"(af[mi][0]), "r"(af[mi][1]), "r"(af[mi][2]), "r"(af[mi][3]),
                      "r"(b0), "r"(b1));
            }
        }
    }

    float rsum[2][2] = {{0.f, 0.f}, {0.f, 0.f}};
    #pragma unroll
    for (int mi = 0; mi < 2; mi++)
        #pragma unroll
        for (int ni = 0; ni < 16; ni++)
            #pragma unroll
            for (int q = 0; q < 4; q++) {
                float e = __expf(acc1[mi][ni][q]);
                acc1[mi][ni][q] = e;
                rsum[mi][q >> 1] += e;
            }
    #pragma unroll
    for (int mi = 0; mi < 2; mi++)
        #pragma unroll
        for (int hf = 0; hf < 2; hf++) {
            float v = rsum[mi][hf];
            v += __shfl_xor_sync(0xFFFFFFFF, v, 1);
            v += __shfl_xor_sync(0xFFFFFFFF, v, 2);
            rsum[mi][hf] = v;
        }

    __syncthreads();

    #pragma unroll
    for (int mi = 0; mi < 2; mi++) {
        int r0 = wid * 32 + mi * 16 + lr;
        if (la3 == 0) {
            shm[AT_RS + r0]     = __float_as_uint(rsum[mi][0]);
            shm[AT_RS + r0 + 8] = __float_as_uint(rsum[mi][1]);
        }
        #pragma unroll
        for (int ni = 0; ni < 16; ni++) {
            int c0 = ni * 8 + la3 * 2;
            shm[AT_PT + (c0 + 0) * 132 + r0]     = f2tf(acc1[mi][ni][0]);
            shm[AT_PT + (c0 + 1) * 132 + r0]     = f2tf(acc1[mi][ni][1]);
            shm[AT_PT + (c0 + 0) * 132 + r0 + 8] = f2tf(acc1[mi][ni][2]);
            shm[AT_PT + (c0 + 1) * 132 + r0 + 8] = f2tf(acc1[mi][ni][3]);
        }
    }
    __syncthreads();

    float acc2[2][4][4];
    #pragma unroll
    for (int mi = 0; mi < 2; mi++)
        #pragma unroll
        for (int ni = 0; ni < 4; ni++)
            #pragma unroll
            for (int q = 0; q < 4; q++) acc2[mi][ni][q] = 0.0f;

    #pragma unroll
    for (int ks = 0; ks < 16; ks++) {
        int kk = ks * 8;
        uint32_t af[2][4];
        #pragma unroll
        for (int mi = 0; mi < 2; mi++) {
            int r = wid * 32 + mi * 16 + lr;
            af[mi][0] = shm[AT_PT + (kk + la3) * 132 + r];
            af[mi][1] = shm[AT_PT + (kk + la3) * 132 + r + 8];
            af[mi][2] = shm[AT_PT + (kk + 4 + la3) * 132 + r];
            af[mi][3] = shm[AT_PT + (kk + 4 + la3) * 132 + r + 8];
        }
        #pragma unroll
        for (int ni = 0; ni < 4; ni++) {
            uint32_t b0 = shm[AT_VS + (kk + la3) * 36 + ni * 8 + lr];
            uint32_t b1 = shm[AT_VS + (kk + 4 + la3) * 36 + ni * 8 + lr];
            #pragma unroll
            for (int mi = 0; mi < 2; mi++) {
                asm volatile(
                    "mma.sync.aligned.m16n8k8.row.col.f32.tf32.tf32.f32 "
                    "{%0,%1,%2,%3}, {%4,%5,%6,%7}, {%8,%9}, {%0,%1,%2,%3};"
                    : "+f"(acc2[mi][ni][0]), "+f"(acc2[mi][ni][1]),
                      "+f"(acc2[mi][ni][2]), "+f"(acc2[mi][ni][3])
                    : "r"(af[mi][0]), "r"(af[mi][1]), "r"(af[mi][2]), "r"(af[mi][3]),
                      "r"(b0), "r"(b1));
            }
        }
    }

    #pragma unroll
    for (int mi = 0; mi < 2; mi++) {
        #pragma unroll
        for (int hf = 0; hf < 2; hf++) {
            int s = wid * 32 + mi * 16 + lr + hf * 8;
            float inv = 1.0f / __uint_as_float(shm[AT_RS + s]);
            const float* gp = g_gate + base + (size_t)s * srow;
            float* op = g_o + base + (size_t)s * srow;
            #pragma unroll
            for (int ni = 0; ni < 4; ni++) {
                int c = ni * 8 + la3 * 2;
                float2 gv = *(const float2*)(gp + c);
                float2 ov;
                ov.x = acc2[mi][ni][hf * 2 + 0] * inv * gv.x;
                ov.y = acc2[mi][ni][hf * 2 + 1] * inv * gv.y;
                *(float2*)(op + c) = ov;
            }
        }
    }
}

// ---------------- launch ----------------
extern "C" void kernel_launch(void* const* d_in, const int* in_sizes, int n_in,
                              void* d_out, int out_size) {
    const float* msa  = (const float*)d_in[0];
    const float* ln_s = (const float*)d_in[1];
    const float* ln_b = (const float*)d_in[2];
    const float* wq   = (const float*)d_in[3];
    const float* wk   = (const float*)d_in[4];
    const float* wv   = (const float*)d_in[5];
    const float* wg   = (const float*)d_in[6];
    const float* bg   = (const float*)d_in[7];
    const float* wo   = (const float*)d_in[8];
    const float* bo   = (const float*)d_in[9];
    float* out = (float*)d_out;

    cudaFuncSetAttribute(attn_tc_kernel, cudaFuncAttributeMaxDynamicSharedMemorySize, ATTN_SMEM);

    ln_kernel<<<ROWS / 8, dim3(32, 8)>>>(msa, ln_s, ln_b);
    transpose_w<<<dim3(8, 8, 5), dim3(32, 8)>>>(wq, wk, wv, wg, wo);
    proj_kernel<<<dim3(ROWS / 128, 8), 128>>>(bg);
    attn_tc_kernel<<<L_DIM * H_DIM, 128, ATTN_SMEM>>>();
    outproj_kernel<<<dim3(ROWS / 128, 2), 128>>>(bo, out);
}

// round 8
// speedup vs baseline: 1.2410x; 1.2410x over previous
#include <cuda_runtime.h>
#include <cuda_bf16.h>
#include <cstdint>
#include <cstddef>
#include <math.h>

// Problem constants
#define S_DIM 128
#define L_DIM 512
#define D_DIM 256
#define H_DIM 8
#define C_DIM 32
#define HC    256
#define ROWS  65536

// ---------------- scratch (device globals; allocation-free) ----------------
__device__ float g_x[(size_t)ROWS * D_DIM];
__device__ float g_q[(size_t)ROWS * HC];
__device__ float g_k[(size_t)ROWS * HC];
__device__ float g_v[(size_t)ROWS * HC];
__device__ float g_gate[(size_t)ROWS * HC];
__device__ float g_o[(size_t)ROWS * HC];
__device__ float g_wT[5 * 256 * 256];   // weights transposed to [n][k]; slots: wq,wk,wv,wg,wo

__device__ __forceinline__ uint32_t f2tf(float f) {
    uint32_t u;
    asm("cvt.rna.tf32.f32 %0, %1;" : "=r"(u) : "f"(f));
    return u;
}
__device__ __forceinline__ uint32_t smem_u32(const void* p) {
    uint32_t a;
    asm("{ .reg .u64 t; cvta.to.shared.u64 t, %1; cvt.u32.u64 %0, t; }" : "=r"(a) : "l"(p));
    return a;
}
__device__ __forceinline__ void ldsm4(uint32_t& r0, uint32_t& r1, uint32_t& r2, uint32_t& r3,
                                      uint32_t addr) {
    asm volatile("ldmatrix.sync.aligned.m8n8.x4.shared.b16 {%0,%1,%2,%3}, [%4];"
                 : "=r"(r0), "=r"(r1), "=r"(r2), "=r"(r3) : "r"(addr));
}

// ---------------- LayerNorm: one warp per row of 256 ----------------
__global__ void __launch_bounds__(256) ln_kernel(const float* __restrict__ in,
                                                 const float* __restrict__ sc,
                                                 const float* __restrict__ bi) {
    int row  = blockIdx.x * blockDim.y + threadIdx.y;
    int lane = threadIdx.x;
    const float4* p = (const float4*)(in + (size_t)row * D_DIM);
    float4 a = p[lane];
    float4 b = p[lane + 32];
    float s  = a.x + a.y + a.z + a.w + b.x + b.y + b.z + b.w;
    float s2 = a.x*a.x + a.y*a.y + a.z*a.z + a.w*a.w
             + b.x*b.x + b.y*b.y + b.z*b.z + b.w*b.w;
    #pragma unroll
    for (int off = 16; off > 0; off >>= 1) {
        s  += __shfl_xor_sync(0xFFFFFFFF, s,  off);
        s2 += __shfl_xor_sync(0xFFFFFFFF, s2, off);
    }
    float mean = s * (1.0f / 256.0f);
    float var  = s2 * (1.0f / 256.0f) - mean * mean;
    float inv  = rsqrtf(var + 1e-5f);

    const float4* scp = (const float4*)sc;
    const float4* bip = (const float4*)bi;
    float4 sa = scp[lane], sb = scp[lane + 32];
    float4 ba = bip[lane], bb = bip[lane + 32];
    float4 oa, ob;
    oa.x = (a.x - mean) * inv * sa.x + ba.x;
    oa.y = (a.y - mean) * inv * sa.y + ba.y;
    oa.z = (a.z - mean) * inv * sa.z + ba.z;
    oa.w = (a.w - mean) * inv * sa.w + ba.w;
    ob.x = (b.x - mean) * inv * sb.x + bb.x;
    ob.y = (b.y - mean) * inv * sb.y + bb.y;
    ob.z = (b.z - mean) * inv * sb.z + bb.z;
    ob.w = (b.w - mean) * inv * sb.w + bb.w;
    float4* q = (float4*)(g_x + (size_t)row * D_DIM);
    q[lane]      = oa;
    q[lane + 32] = ob;
}

// ---------------- weight transpose: g_wT[z][n][k] = W_z[k][n] ----------------
__global__ void __launch_bounds__(256) transpose_w(const float* __restrict__ wq,
                                                   const float* __restrict__ wk,
                                                   const float* __restrict__ wv,
                                                   const float* __restrict__ wg,
                                                   const float* __restrict__ wo) {
    const float* srcs[5] = {wq, wk, wv, wg, wo};
    const float* src = srcs[blockIdx.z];
    float* dst = g_wT + (size_t)blockIdx.z * 65536;
    __shared__ float t[32][33];
    int tx = threadIdx.x, ty = threadIdx.y;
    int x  = blockIdx.x * 32 + tx;
    int y0 = blockIdx.y * 32;
    #pragma unroll
    for (int j = 0; j < 32; j += 8)
        t[ty + j][tx] = src[(size_t)(y0 + ty + j) * 256 + x];
    __syncthreads();
    int nx = blockIdx.y * 32 + tx;
    #pragma unroll
    for (int j = 0; j < 32; j += 8)
        dst[(size_t)(blockIdx.x * 32 + ty + j) * 256 + nx] = t[tx][ty + j];
}

// ---------------- TF32 GEMM: 128x128 tile, K=256, ldmatrix + coalesced staging ----------------
// A: rows x 256 row-major (k-major). Bt: [n][k] k-major (pre-transposed weights).
// smem rows: [tile_row][16 + pad4] words; stride 20 words -> LDSM quads (5r+k)%8 distinct.
#define BKW 20

__device__ __forceinline__ void gemm_ldsm_tile(const float* __restrict__ A,
                                               const float* __restrict__ Bt,
                                               int row0, int col0,
                                               float* __restrict__ Cout, int ldc,
                                               const float* __restrict__ bias,
                                               bool do_sig) {
    __shared__ uint32_t As[128 * BKW];
    __shared__ uint32_t Bs[128 * BKW];

    int tid  = threadIdx.x;
    int lane = tid & 31;
    int wid  = tid >> 5;
    int wm   = wid & 1;
    int wn   = wid >> 1;
    int la3  = lane & 3;
    int lr   = lane >> 2;

    uint32_t sA = smem_u32(As);
    uint32_t sB = smem_u32(Bs);

    // per-lane LDSM base addresses (tile layout: t0=(r,k) t1=(r+8,k) t2=(r,k+4) t3=(r+8,k+4))
    int tileid = lane >> 3;
    int lrow   = lane & 7;
    uint32_t aAddr = sA + (((uint32_t)(wm * 64 + (tileid & 1) * 8 + lrow)) * BKW
                           + (uint32_t)(tileid >> 1) * 4) * 4;
    uint32_t bAddr = sB + (((uint32_t)(wn * 64 + (tileid & 1) * 8 + lrow)) * BKW
                           + (uint32_t)(tileid >> 1) * 4) * 4;

    float acc[4][8][4];
    #pragma unroll
    for (int mi = 0; mi < 4; mi++)
        #pragma unroll
        for (int ni = 0; ni < 8; ni++)
            #pragma unroll
            for (int q = 0; q < 4; q++) acc[mi][ni][q] = 0.0f;

    // coalesced global loads: t = tid + i*128; row = t>>2; kq = (t&3)*4
    float4 pa[4], pb[4];
    #pragma unroll
    for (int i = 0; i < 4; i++) {
        int t = tid + i * 128;
        int m = t >> 2, kq = (t & 3) * 4;
        pa[i] = *(const float4*)(A  + (size_t)(row0 + m) * 256 + kq);
        pb[i] = *(const float4*)(Bt + (size_t)(col0 + m) * 256 + kq);
    }

    for (int c = 0; c < 16; c++) {
        // stage chunk c: regs -> smem (uint4 stores into padded rows)
        #pragma unroll
        for (int i = 0; i < 4; i++) {
            int t = tid + i * 128;
            int m = t >> 2, kq = (t & 3) * 4;
            uint4 ua, ub;
            ua.x = f2tf(pa[i].x); ua.y = f2tf(pa[i].y); ua.z = f2tf(pa[i].z); ua.w = f2tf(pa[i].w);
            ub.x = f2tf(pb[i].x); ub.y = f2tf(pb[i].y); ub.z = f2tf(pb[i].z); ub.w = f2tf(pb[i].w);
            *(uint4*)&As[m * BKW + kq] = ua;
            *(uint4*)&Bs[m * BKW + kq] = ub;
        }
        __syncthreads();

        if (c < 15) {
            #pragma unroll
            for (int i = 0; i < 4; i++) {
                int t = tid + i * 128;
                int m = t >> 2, kq = (t & 3) * 4;
                pa[i] = *(const float4*)(A  + (size_t)(row0 + m) * 256 + (c + 1) * 16 + kq);
                pb[i] = *(const float4*)(Bt + (size_t)(col0 + m) * 256 + (c + 1) * 16 + kq);
            }
        }

        #pragma unroll
        for (int kk = 0; kk < 16; kk += 8) {
            uint32_t af[4][4];
            #pragma unroll
            for (int mi = 0; mi < 4; mi++)
                ldsm4(af[mi][0], af[mi][1], af[mi][2], af[mi][3],
                      aAddr + (uint32_t)(mi * 16 * BKW + kk) * 4);
            uint32_t bf[8][2];
            #pragma unroll
            for (int j = 0; j < 4; j++) {
                uint32_t r0, r1, r2, r3;
                ldsm4(r0, r1, r2, r3, bAddr + (uint32_t)(j * 16 * BKW + kk) * 4);
                bf[2 * j + 0][0] = r0; bf[2 * j + 1][0] = r1;
                bf[2 * j + 0][1] = r2; bf[2 * j + 1][1] = r3;
            }
            #pragma unroll
            for (int mi = 0; mi < 4; mi++)
                #pragma unroll
                for (int ni = 0; ni < 8; ni++) {
                    asm volatile(
                        "mma.sync.aligned.m16n8k8.row.col.f32.tf32.tf32.f32 "
                        "{%0,%1,%2,%3}, {%4,%5,%6,%7}, {%8,%9}, {%0,%1,%2,%3};"
                        : "+f"(acc[mi][ni][0]), "+f"(acc[mi][ni][1]),
                          "+f"(acc[mi][ni][2]), "+f"(acc[mi][ni][3])
                        : "r"(af[mi][0]), "r"(af[mi][1]), "r"(af[mi][2]), "r"(af[mi][3]),
                          "r"(bf[ni][0]), "r"(bf[ni][1]));
                }
        }
        __syncthreads();
    }

    #pragma unroll
    for (int mi = 0; mi < 4; mi++) {
        #pragma unroll
        for (int half = 0; half < 2; half++) {
            int rg = row0 + wm * 64 + mi * 16 + lr + half * 8;
            #pragma unroll
            for (int ni = 0; ni < 8; ni++) {
                int cg = col0 + wn * 64 + ni * 8 + la3 * 2;
                float v0 = acc[mi][ni][half * 2 + 0];
                float v1 = acc[mi][ni][half * 2 + 1];
                if (bias) { v0 += bias[cg]; v1 += bias[cg + 1]; }
                if (do_sig) {
                    v0 = 1.0f / (1.0f + __expf(-v0));
                    v1 = 1.0f / (1.0f + __expf(-v1));
                }
                *(float2*)(Cout + (size_t)rg * ldc + cg) = make_float2(v0, v1);
            }
        }
    }
}

__global__ void __launch_bounds__(128) proj_kernel(const float* __restrict__ bg) {
    int row0 = blockIdx.x * 128;
    int nblk = blockIdx.y;          // 0..7
    int wsel = nblk >> 1;
    int colW = (nblk & 1) * 128;
    const float* Bt = g_wT + (size_t)wsel * 65536;
    float* out;
    const float* bias = nullptr;
    bool sig = false;
    switch (wsel) {
        case 0: out = g_q; break;
        case 1: out = g_k; break;
        case 2: out = g_v; break;
        default: out = g_gate; bias = bg; sig = true; break;
    }
    gemm_ldsm_tile(g_x, Bt, row0, colW, out, HC, bias, sig);
}

__global__ void __launch_bounds__(128) outproj_kernel(const float* __restrict__ bo,
                                                      float* __restrict__ out) {
    int row0 = blockIdx.x * 128;
    int colW = blockIdx.y * 128;
    gemm_ldsm_tile(g_o, g_wT + 4 * 65536, row0, colW, out, D_DIM, bo, false);
}

// ---------------- tensor-core attention per (l, h) (R6 proven version) ----------------
#define AT_QS 0
#define AT_KS 4224
#define AT_PT 0
#define AT_VS 16896
#define AT_RS 21504
#define ATTN_SMEM ((21504 + 128) * 4)

__global__ void __launch_bounds__(128) attn_tc_kernel() {
    extern __shared__ uint32_t shm[];
    int l = blockIdx.x >> 3;
    int h = blockIdx.x & 7;
    int tid  = threadIdx.x;
    int lane = tid & 31;
    int wid  = tid >> 5;
    int la3  = lane & 3;
    int lr   = lane >> 2;

    const size_t srow = (size_t)L_DIM * HC;
    const size_t base = (size_t)l * HC + (size_t)h * C_DIM;
    const float scale = 0.17677669529663687f;

    {
        int tloc = tid >> 3;
        int cq   = (tid & 7) * 4;
        #pragma unroll
        for (int p = 0; p < 8; p++) {
            int r = p * 16 + tloc;
            size_t gi = base + (size_t)r * srow + cq;
            float4 qv = *(const float4*)(g_q + gi);
            shm[AT_QS + (cq + 0) * 132 + r] = f2tf(qv.x * scale);
            shm[AT_QS + (cq + 1) * 132 + r] = f2tf(qv.y * scale);
            shm[AT_QS + (cq + 2) * 132 + r] = f2tf(qv.z * scale);
            shm[AT_QS + (cq + 3) * 132 + r] = f2tf(qv.w * scale);
            float4 kv = *(const float4*)(g_k + gi);
            shm[AT_KS + (cq + 0) * 132 + r] = f2tf(kv.x);
            shm[AT_KS + (cq + 1) * 132 + r] = f2tf(kv.y);
            shm[AT_KS + (cq + 2) * 132 + r] = f2tf(kv.z);
            shm[AT_KS + (cq + 3) * 132 + r] = f2tf(kv.w);
            float4 vv = *(const float4*)(g_v + gi);
            uint4 u;
            u.x = f2tf(vv.x); u.y = f2tf(vv.y); u.z = f2tf(vv.z); u.w = f2tf(vv.w);
            *(uint4*)&shm[AT_VS + r * 36 + cq] = u;
        }
    }
    __syncthreads();

    float acc1[2][16][4];
    #pragma unroll
    for (int mi = 0; mi < 2; mi++)
        #pragma unroll
        for (int ni = 0; ni < 16; ni++)
            #pragma unroll
            for (int q = 0; q < 4; q++) acc1[mi][ni][q] = 0.0f;

    #pragma unroll
    for (int ks = 0; ks < 4; ks++) {
        int kk = ks * 8;
        uint32_t af[2][4];
        #pragma unroll
        for (int mi = 0; mi < 2; mi++) {
            int r = wid * 32 + mi * 16 + lr;
            af[mi][0] = shm[AT_QS + (kk + la3) * 132 + r];
            af[mi][1] = shm[AT_QS + (kk + la3) * 132 + r + 8];
            af[mi][2] = shm[AT_QS + (kk + 4 + la3) * 132 + r];
            af[mi][3] = shm[AT_QS + (kk + 4 + la3) * 132 + r + 8];
        }
        #pragma unroll
        for (int ni = 0; ni < 16; ni++) {
            uint32_t b0 = shm[AT_KS + (kk + la3) * 132 + ni * 8 + lr];
            uint32_t b1 = shm[AT_KS + (kk + 4 + la3) * 132 + ni * 8 + lr];
            #pragma unroll
            for (int mi = 0; mi < 2; mi++) {
                asm volatile(
                    "mma.sync.aligned.m16n8k8.row.col.f32.tf32.tf32.f32 "
                    "{%0,%1,%2,%3}, {%4,%5,%6,%7}, {%8,%9}, {%0,%1,%2,%3};"
                    : "+f"(acc1[mi][ni][0]), "+f"(acc1[mi][ni][1]),
                      "+f"(acc1[mi][ni][2]), "+f"(acc1[mi][ni][3])
                    : "r"(af[mi][0]), "r"(af[mi][1]), "r"(af[mi][2]), "r"(af[mi][3]),
                      "r"(b0), "r"(b1));
            }
        }
    }

    float rsum[2][2] = {{0.f, 0.f}, {0.f, 0.f}};
    #pragma unroll
    for (int mi = 0; mi < 2; mi++)
        #pragma unroll
        for (int ni = 0; ni < 16; ni++)
            #pragma unroll
            for (int q = 0; q < 4; q++) {
                float e = __expf(acc1[mi][ni][q]);
                acc1[mi][ni][q] = e;
                rsum[mi][q >> 1] += e;
            }
    #pragma unroll
    for (int mi = 0; mi < 2; mi++)
        #pragma unroll
        for (int hf = 0; hf < 2; hf++) {
            float v = rsum[mi][hf];
            v += __shfl_xor_sync(0xFFFFFFFF, v, 1);
            v += __shfl_xor_sync(0xFFFFFFFF, v, 2);
            rsum[mi][hf] = v;
        }

    __syncthreads();

    #pragma unroll
    for (int mi = 0; mi < 2; mi++) {
        int r0 = wid * 32 + mi * 16 + lr;
        if (la3 == 0) {
            shm[AT_RS + r0]     = __float_as_uint(rsum[mi][0]);
            shm[AT_RS + r0 + 8] = __float_as_uint(rsum[mi][1]);
        }
        #pragma unroll
        for (int ni = 0; ni < 16; ni++) {
            int c0 = ni * 8 + la3 * 2;
            shm[AT_PT + (c0 + 0) * 132 + r0]     = f2tf(acc1[mi][ni][0]);
            shm[AT_PT + (c0 + 1) * 132 + r0]     = f2tf(acc1[mi][ni][1]);
            shm[AT_PT + (c0 + 0) * 132 + r0 + 8] = f2tf(acc1[mi][ni][2]);
            shm[AT_PT + (c0 + 1) * 132 + r0 + 8] = f2tf(acc1[mi][ni][3]);
        }
    }
    __syncthreads();

    float acc2[2][4][4];
    #pragma unroll
    for (int mi = 0; mi < 2; mi++)
        #pragma unroll
        for (int ni = 0; ni < 4; ni++)
            #pragma unroll
            for (int q = 0; q < 4; q++) acc2[mi][ni][q] = 0.0f;

    #pragma unroll
    for (int ks = 0; ks < 16; ks++) {
        int kk = ks * 8;
        uint32_t af[2][4];
        #pragma unroll
        for (int mi = 0; mi < 2; mi++) {
            int r = wid * 32 + mi * 16 + lr;
            af[mi][0] = shm[AT_PT + (kk + la3) * 132 + r];
            af[mi][1] = shm[AT_PT + (kk + la3) * 132 + r + 8];
            af[mi][2] = shm[AT_PT + (kk + 4 + la3) * 132 + r];
            af[mi][3] = shm[AT_PT + (kk + 4 + la3) * 132 + r + 8];
        }
        #pragma unroll
        for (int ni = 0; ni < 4; ni++) {
            uint32_t b0 = shm[AT_VS + (kk + la3) * 36 + ni * 8 + lr];
            uint32_t b1 = shm[AT_VS + (kk + 4 + la3) * 36 + ni * 8 + lr];
            #pragma unroll
            for (int mi = 0; mi < 2; mi++) {
                asm volatile(
                    "mma.sync.aligned.m16n8k8.row.col.f32.tf32.tf32.f32 "
                    "{%0,%1,%2,%3}, {%4,%5,%6,%7}, {%8,%9}, {%0,%1,%2,%3};"
                    : "+f"(acc2[mi][ni][0]), "+f"(acc2[mi][ni][1]),
                      "+f"(acc2[mi][ni][2]), "+f"(acc2[mi][ni][3])
                    : "r"(af[mi][0]), "r"(af[mi][1]), "r"(af[mi][2]), "r"(af[mi][3]),
                      "r"(b0), "r"(b1));
            }
        }
    }

    #pragma unroll
    for (int mi = 0; mi < 2; mi++) {
        #pragma unroll
        for (int hf = 0; hf < 2; hf++) {
            int s = wid * 32 + mi * 16 + lr + hf * 8;
            float inv = 1.0f / __uint_as_float(shm[AT_RS + s]);
            const float* gp = g_gate + base + (size_t)s * srow;
            float* op = g_o + base + (size_t)s * srow;
            #pragma unroll
            for (int ni = 0; ni < 4; ni++) {
                int c = ni * 8 + la3 * 2;
                float2 gv = *(const float2*)(gp + c);
                float2 ov;
                ov.x = acc2[mi][ni][hf * 2 + 0] * inv * gv.x;
                ov.y = acc2[mi][ni][hf * 2 + 1] * inv * gv.y;
                *(float2*)(op + c) = ov;
            }
        }
    }
}

// ---------------- launch ----------------
extern "C" void kernel_launch(void* const* d_in, const int* in_sizes, int n_in,
                              void* d_out, int out_size) {
    const float* msa  = (const float*)d_in[0];
    const float* ln_s = (const float*)d_in[1];
    const float* ln_b = (const float*)d_in[2];
    const float* wq   = (const float*)d_in[3];
    const float* wk   = (const float*)d_in[4];
    const float* wv   = (const float*)d_in[5];
    const float* wg   = (const float*)d_in[6];
    const float* bg   = (const float*)d_in[7];
    const float* wo   = (const float*)d_in[8];
    const float* bo   = (const float*)d_in[9];
    float* out = (float*)d_out;

    cudaFuncSetAttribute(attn_tc_kernel, cudaFuncAttributeMaxDynamicSharedMemorySize, ATTN_SMEM);

    ln_kernel<<<ROWS / 8, dim3(32, 8)>>>(msa, ln_s, ln_b);
    transpose_w<<<dim3(8, 8, 5), dim3(32, 8)>>>(wq, wk, wv, wg, wo);
    proj_kernel<<<dim3(ROWS / 128, 8), 128>>>(bg);
    attn_tc_kernel<<<L_DIM * H_DIM, 128, ATTN_SMEM>>>();
    outproj_kernel<<<dim3(ROWS / 128, 2), 128>>>(bo, out);
}

// round 9
// speedup vs baseline: 1.4231x; 1.1467x over previous
#include <cuda_runtime.h>
#include <cuda_bf16.h>
#include <cstdint>
#include <cstddef>
#include <math.h>

// Problem constants
#define S_DIM 128
#define L_DIM 512
#define D_DIM 256
#define H_DIM 8
#define C_DIM 32
#define HC    256
#define ROWS  65536

// ---------------- scratch (device globals; allocation-free) ----------------
__device__ float g_x[(size_t)ROWS * D_DIM];
__device__ float g_q[(size_t)ROWS * HC];
__device__ float g_k[(size_t)ROWS * HC];
__device__ float g_v[(size_t)ROWS * HC];
__device__ float g_gate[(size_t)ROWS * HC];
__device__ float g_o[(size_t)ROWS * HC];
__device__ float g_wT[5 * 256 * 256];   // weights transposed to [n][k]

__device__ __forceinline__ uint32_t f2tf(float f) {
    uint32_t u;
    asm("cvt.rna.tf32.f32 %0, %1;" : "=r"(u) : "f"(f));
    return u;
}
__device__ __forceinline__ uint32_t smem_u32(const void* p) {
    uint32_t a;
    asm("{ .reg .u64 t; cvta.to.shared.u64 t, %1; cvt.u32.u64 %0, t; }" : "=r"(a) : "l"(p));
    return a;
}
__device__ __forceinline__ void ldsm4(uint32_t& r0, uint32_t& r1, uint32_t& r2, uint32_t& r3,
                                      uint32_t addr) {
    asm volatile("ldmatrix.sync.aligned.m8n8.x4.shared.b16 {%0,%1,%2,%3}, [%4];"
                 : "=r"(r0), "=r"(r1), "=r"(r2), "=r"(r3) : "r"(addr));
}
__device__ __forceinline__ void mma8(float* c, const uint32_t* a, uint32_t b0, uint32_t b1) {
    asm volatile(
        "mma.sync.aligned.m16n8k8.row.col.f32.tf32.tf32.f32 "
        "{%0,%1,%2,%3}, {%4,%5,%6,%7}, {%8,%9}, {%0,%1,%2,%3};"
        : "+f"(c[0]), "+f"(c[1]), "+f"(c[2]), "+f"(c[3])
        : "r"(a[0]), "r"(a[1]), "r"(a[2]), "r"(a[3]), "r"(b0), "r"(b1));
}

// ---------------- LayerNorm: one warp per row of 256 ----------------
__global__ void __launch_bounds__(256) ln_kernel(const float* __restrict__ in,
                                                 const float* __restrict__ sc,
                                                 const float* __restrict__ bi) {
    int row  = blockIdx.x * blockDim.y + threadIdx.y;
    int lane = threadIdx.x;
    const float4* p = (const float4*)(in + (size_t)row * D_DIM);
    float4 a = p[lane];
    float4 b = p[lane + 32];
    float s  = a.x + a.y + a.z + a.w + b.x + b.y + b.z + b.w;
    float s2 = a.x*a.x + a.y*a.y + a.z*a.z + a.w*a.w
             + b.x*b.x + b.y*b.y + b.z*b.z + b.w*b.w;
    #pragma unroll
    for (int off = 16; off > 0; off >>= 1) {
        s  += __shfl_xor_sync(0xFFFFFFFF, s,  off);
        s2 += __shfl_xor_sync(0xFFFFFFFF, s2, off);
    }
    float mean = s * (1.0f / 256.0f);
    float var  = s2 * (1.0f / 256.0f) - mean * mean;
    float inv  = rsqrtf(var + 1e-5f);

    const float4* scp = (const float4*)sc;
    const float4* bip = (const float4*)bi;
    float4 sa = scp[lane], sb = scp[lane + 32];
    float4 ba = bip[lane], bb = bip[lane + 32];
    float4 oa, ob;
    oa.x = (a.x - mean) * inv * sa.x + ba.x;
    oa.y = (a.y - mean) * inv * sa.y + ba.y;
    oa.z = (a.z - mean) * inv * sa.z + ba.z;
    oa.w = (a.w - mean) * inv * sa.w + ba.w;
    ob.x = (b.x - mean) * inv * sb.x + bb.x;
    ob.y = (b.y - mean) * inv * sb.y + bb.y;
    ob.z = (b.z - mean) * inv * sb.z + bb.z;
    ob.w = (b.w - mean) * inv * sb.w + bb.w;
    float4* q = (float4*)(g_x + (size_t)row * D_DIM);
    q[lane]      = oa;
    q[lane + 32] = ob;
}

// ---------------- weight transpose ----------------
__global__ void __launch_bounds__(256) transpose_w(const float* __restrict__ wq,
                                                   const float* __restrict__ wk,
                                                   const float* __restrict__ wv,
                                                   const float* __restrict__ wg,
                                                   const float* __restrict__ wo) {
    const float* srcs[5] = {wq, wk, wv, wg, wo};
    const float* src = srcs[blockIdx.z];
    float* dst = g_wT + (size_t)blockIdx.z * 65536;
    __shared__ float t[32][33];
    int tx = threadIdx.x, ty = threadIdx.y;
    int x  = blockIdx.x * 32 + tx;
    int y0 = blockIdx.y * 32;
    #pragma unroll
    for (int j = 0; j < 32; j += 8)
        t[ty + j][tx] = src[(size_t)(y0 + ty + j) * 256 + x];
    __syncthreads();
    int nx = blockIdx.y * 32 + tx;
    #pragma unroll
    for (int j = 0; j < 32; j += 8)
        dst[(size_t)(blockIdx.x * 32 + ty + j) * 256 + nx] = t[tx][ty + j];
}

// ---------------- TF32 GEMM: 128x128 tile, 256 threads, ldmatrix ----------------
#define BKW 20

__device__ __forceinline__ void gemm_ldsm_tile(const float* __restrict__ A,
                                               const float* __restrict__ Bt,
                                               int row0, int col0,
                                               float* __restrict__ Cout, int ldc,
                                               const float* __restrict__ bias,
                                               bool do_sig) {
    __shared__ uint32_t As[128 * BKW];
    __shared__ uint32_t Bs[128 * BKW];

    int tid  = threadIdx.x;             // 0..255
    int lane = tid & 31;
    int wid  = tid >> 5;                // 0..7
    int wm   = wid & 1;                 // 2 M halves of 64
    int wn   = wid >> 1;                // 4 N quarters of 32
    int la3  = lane & 3;
    int lr   = lane >> 2;

    uint32_t sA = smem_u32(As);
    uint32_t sB = smem_u32(Bs);

    int tileid = lane >> 3;
    int lrow   = lane & 7;
    uint32_t aAddr = sA + (((uint32_t)(wm * 64 + (tileid & 1) * 8 + lrow)) * BKW
                           + (uint32_t)(tileid >> 1) * 4) * 4;
    uint32_t bAddr = sB + (((uint32_t)(wn * 32 + (tileid & 1) * 8 + lrow)) * BKW
                           + (uint32_t)(tileid >> 1) * 4) * 4;

    float acc[4][4][4];
    #pragma unroll
    for (int mi = 0; mi < 4; mi++)
        #pragma unroll
        for (int ni = 0; ni < 4; ni++)
            #pragma unroll
            for (int q = 0; q < 4; q++) acc[mi][ni][q] = 0.0f;

    float4 pa[2], pb[2];
    #pragma unroll
    for (int i = 0; i < 2; i++) {
        int t = tid + i * 256;
        int m = t >> 2, kq = (t & 3) * 4;
        pa[i] = *(const float4*)(A  + (size_t)(row0 + m) * 256 + kq);
        pb[i] = *(const float4*)(Bt + (size_t)(col0 + m) * 256 + kq);
    }

    for (int c = 0; c < 16; c++) {
        #pragma unroll
        for (int i = 0; i < 2; i++) {
            int t = tid + i * 256;
            int m = t >> 2, kq = (t & 3) * 4;
            uint4 ua, ub;
            ua.x = f2tf(pa[i].x); ua.y = f2tf(pa[i].y); ua.z = f2tf(pa[i].z); ua.w = f2tf(pa[i].w);
            ub.x = f2tf(pb[i].x); ub.y = f2tf(pb[i].y); ub.z = f2tf(pb[i].z); ub.w = f2tf(pb[i].w);
            *(uint4*)&As[m * BKW + kq] = ua;
            *(uint4*)&Bs[m * BKW + kq] = ub;
        }
        __syncthreads();

        if (c < 15) {
            #pragma unroll
            for (int i = 0; i < 2; i++) {
                int t = tid + i * 256;
                int m = t >> 2, kq = (t & 3) * 4;
                pa[i] = *(const float4*)(A  + (size_t)(row0 + m) * 256 + (c + 1) * 16 + kq);
                pb[i] = *(const float4*)(Bt + (size_t)(col0 + m) * 256 + (c + 1) * 16 + kq);
            }
        }

        #pragma unroll
        for (int kk = 0; kk < 16; kk += 8) {
            uint32_t af[4][4];
            #pragma unroll
            for (int mi = 0; mi < 4; mi++)
                ldsm4(af[mi][0], af[mi][1], af[mi][2], af[mi][3],
                      aAddr + (uint32_t)(mi * 16 * BKW + kk) * 4);
            uint32_t bf[4][2];
            #pragma unroll
            for (int j = 0; j < 2; j++) {
                uint32_t r0, r1, r2, r3;
                ldsm4(r0, r1, r2, r3, bAddr + (uint32_t)(j * 16 * BKW + kk) * 4);
                bf[2 * j + 0][0] = r0; bf[2 * j + 1][0] = r1;
                bf[2 * j + 0][1] = r2; bf[2 * j + 1][1] = r3;
            }
            #pragma unroll
            for (int mi = 0; mi < 4; mi++)
                #pragma unroll
                for (int ni = 0; ni < 4; ni++)
                    mma8(acc[mi][ni], af[mi], bf[ni][0], bf[ni][1]);
        }
        __syncthreads();
    }

    #pragma unroll
    for (int mi = 0; mi < 4; mi++) {
        #pragma unroll
        for (int half = 0; half < 2; half++) {
            int rg = row0 + wm * 64 + mi * 16 + lr + half * 8;
            #pragma unroll
            for (int ni = 0; ni < 4; ni++) {
                int cg = col0 + wn * 32 + ni * 8 + la3 * 2;
                float v0 = acc[mi][ni][half * 2 + 0];
                float v1 = acc[mi][ni][half * 2 + 1];
                if (bias) { v0 += bias[cg]; v1 += bias[cg + 1]; }
                if (do_sig) {
                    v0 = 1.0f / (1.0f + __expf(-v0));
                    v1 = 1.0f / (1.0f + __expf(-v1));
                }
                *(float2*)(Cout + (size_t)rg * ldc + cg) = make_float2(v0, v1);
            }
        }
    }
}

__global__ void __launch_bounds__(256, 2) proj_kernel(const float* __restrict__ bg) {
    int row0 = blockIdx.x * 128;
    int nblk = blockIdx.y;
    int wsel = nblk >> 1;
    int colW = (nblk & 1) * 128;
    const float* Bt = g_wT + (size_t)wsel * 65536;
    float* out;
    const float* bias = nullptr;
    bool sig = false;
    switch (wsel) {
        case 0: out = g_q; break;
        case 1: out = g_k; break;
        case 2: out = g_v; break;
        default: out = g_gate; bias = bg; sig = true; break;
    }
    gemm_ldsm_tile(g_x, Bt, row0, colW, out, HC, bias, sig);
}

__global__ void __launch_bounds__(256, 2) outproj_kernel(const float* __restrict__ bo,
                                                         float* __restrict__ out) {
    int row0 = blockIdx.x * 128;
    int colW = blockIdx.y * 128;
    gemm_ldsm_tile(g_o, g_wT + 4 * 65536, row0, colW, out, D_DIM, bo, false);
}

// ---------------- attention: register-resident P, interleaved phases ----------------
// Qs/Ks/Vs row-major [128][36] words (tf32). No P buffer, no rowsum smem.
#define ATW 36
#define ATTN_SMEM (3 * 128 * ATW * 4)   // 55296 B

__global__ void __launch_bounds__(128) attn_tc_kernel() {
    extern __shared__ uint32_t shm[];
    uint32_t* Qs = shm;
    uint32_t* Ks = shm + 128 * ATW;
    uint32_t* Vs = shm + 2 * 128 * ATW;

    int l = blockIdx.x >> 3;
    int h = blockIdx.x & 7;
    int tid  = threadIdx.x;
    int lane = tid & 31;
    int wid  = tid >> 5;
    int la3  = lane & 3;
    int lr   = lane >> 2;

    const size_t srow = (size_t)L_DIM * HC;
    const size_t base = (size_t)l * HC + (size_t)h * C_DIM;
    const float scale = 0.17677669529663687f;

    // ---- stage Q (pre-scaled), K, V row-major [r][c] ----
    {
        int tloc = tid >> 3;
        int cq   = (tid & 7) * 4;
        #pragma unroll
        for (int p = 0; p < 8; p++) {
            int r = p * 16 + tloc;
            size_t gi = base + (size_t)r * srow + cq;
            float4 qv = *(const float4*)(g_q + gi);
            uint4 uq;
            uq.x = f2tf(qv.x * scale); uq.y = f2tf(qv.y * scale);
            uq.z = f2tf(qv.z * scale); uq.w = f2tf(qv.w * scale);
            *(uint4*)&Qs[r * ATW + cq] = uq;
            float4 kv = *(const float4*)(g_k + gi);
            uint4 uk;
            uk.x = f2tf(kv.x); uk.y = f2tf(kv.y); uk.z = f2tf(kv.z); uk.w = f2tf(kv.w);
            *(uint4*)&Ks[r * ATW + cq] = uk;
            float4 vv = *(const float4*)(g_v + gi);
            uint4 uv;
            uv.x = f2tf(vv.x); uv.y = f2tf(vv.y); uv.z = f2tf(vv.z); uv.w = f2tf(vv.w);
            *(uint4*)&Vs[r * ATW + cq] = uv;
        }
    }
    __syncthreads();

    // ---- preload phase-1 A fragments (Q rows for this warp, all 32 k) ----
    uint32_t af1[4][2][4];
    #pragma unroll
    for (int kk = 0; kk < 4; kk++)
        #pragma unroll
        for (int mi = 0; mi < 2; mi++) {
            int r = wid * 32 + mi * 16 + lr;
            int c = kk * 8 + la3;
            af1[kk][mi][0] = Qs[r * ATW + c];
            af1[kk][mi][1] = Qs[(r + 8) * ATW + c];
            af1[kk][mi][2] = Qs[r * ATW + c + 4];
            af1[kk][mi][3] = Qs[(r + 8) * ATW + c + 4];
        }

    float acc2[2][4][4];
    #pragma unroll
    for (int mi = 0; mi < 2; mi++)
        #pragma unroll
        for (int ni = 0; ni < 4; ni++)
            #pragma unroll
            for (int q = 0; q < 4; q++) acc2[mi][ni][q] = 0.0f;
    float rsum[2][2] = {{0.f, 0.f}, {0.f, 0.f}};

    int srcA = (lane & 28) | (la3 >> 1);
    int srcB = srcA | 2;
    int sel  = la3 & 1;

    // ---- per 8-col S block: S -> exp -> shuffle to A-frag -> P@V ----
    for (int ni = 0; ni < 16; ni++) {
        float s[2][4];
        #pragma unroll
        for (int mi = 0; mi < 2; mi++)
            #pragma unroll
            for (int q = 0; q < 4; q++) s[mi][q] = 0.0f;

        #pragma unroll
        for (int kk = 0; kk < 4; kk++) {
            int t = ni * 8 + lr;
            int c = kk * 8 + la3;
            uint32_t b0 = Ks[t * ATW + c];
            uint32_t b1 = Ks[t * ATW + c + 4];
            mma8(s[0], af1[kk][0], b0, b1);
            mma8(s[1], af1[kk][1], b0, b1);
        }

        float e[2][4];
        #pragma unroll
        for (int mi = 0; mi < 2; mi++)
            #pragma unroll
            for (int q = 0; q < 4; q++) {
                float ev = __expf(s[mi][q]);
                e[mi][q] = ev;
                rsum[mi][q >> 1] += ev;
            }

        // shuffle c-layout -> a-layout (P[r][ni*8+la3] etc.)
        uint32_t a2[2][4];
        #pragma unroll
        for (int mi = 0; mi < 2; mi++) {
            float v0 = __shfl_sync(0xFFFFFFFF, e[mi][0], srcA);
            float v1 = __shfl_sync(0xFFFFFFFF, e[mi][1], srcA);
            float v2 = __shfl_sync(0xFFFFFFFF, e[mi][2], srcA);
            float v3 = __shfl_sync(0xFFFFFFFF, e[mi][3], srcA);
            float w0 = __shfl_sync(0xFFFFFFFF, e[mi][0], srcB);
            float w1 = __shfl_sync(0xFFFFFFFF, e[mi][1], srcB);
            float w2 = __shfl_sync(0xFFFFFFFF, e[mi][2], srcB);
            float w3 = __shfl_sync(0xFFFFFFFF, e[mi][3], srcB);
            a2[mi][0] = f2tf(sel ? v1 : v0);
            a2[mi][1] = f2tf(sel ? v3 : v2);
            a2[mi][2] = f2tf(sel ? w1 : w0);
            a2[mi][3] = f2tf(sel ? w3 : w2);
        }

        #pragma unroll
        for (int ni2 = 0; ni2 < 4; ni2++) {
            int t = ni * 8 + la3;
            uint32_t b0 = Vs[t * ATW + ni2 * 8 + lr];
            uint32_t b1 = Vs[(t + 4) * ATW + ni2 * 8 + lr];
            mma8(acc2[0][ni2], a2[0], b0, b1);
            mma8(acc2[1][ni2], a2[1], b0, b1);
        }
    }

    // ---- reduce row sums across the 4-lane quad ----
    #pragma unroll
    for (int mi = 0; mi < 2; mi++)
        #pragma unroll
        for (int hf = 0; hf < 2; hf++) {
            float v = rsum[mi][hf];
            v += __shfl_xor_sync(0xFFFFFFFF, v, 1);
            v += __shfl_xor_sync(0xFFFFFFFF, v, 2);
            rsum[mi][hf] = v;
        }

    // ---- epilogue: normalize, gate, store ----
    #pragma unroll
    for (int mi = 0; mi < 2; mi++) {
        #pragma unroll
        for (int hf = 0; hf < 2; hf++) {
            int s = wid * 32 + mi * 16 + lr + hf * 8;
            float inv = 1.0f / rsum[mi][hf];
            const float* gp = g_gate + base + (size_t)s * srow;
            float* op = g_o + base + (size_t)s * srow;
            #pragma unroll
            for (int ni2 = 0; ni2 < 4; ni2++) {
                int c = ni2 * 8 + la3 * 2;
                float2 gv = *(const float2*)(gp + c);
                float2 ov;
                ov.x = acc2[mi][ni2][hf * 2 + 0] * inv * gv.x;
                ov.y = acc2[mi][ni2][hf * 2 + 1] * inv * gv.y;
                *(float2*)(op + c) = ov;
            }
        }
    }
}

// ---------------- launch ----------------
extern "C" void kernel_launch(void* const* d_in, const int* in_sizes, int n_in,
                              void* d_out, int out_size) {
    const float* msa  = (const float*)d_in[0];
    const float* ln_s = (const float*)d_in[1];
    const float* ln_b = (const float*)d_in[2];
    const float* wq   = (const float*)d_in[3];
    const float* wk   = (const float*)d_in[4];
    const float* wv   = (const float*)d_in[5];
    const float* wg   = (const float*)d_in[6];
    const float* bg   = (const float*)d_in[7];
    const float* wo   = (const float*)d_in[8];
    const float* bo   = (const float*)d_in[9];
    float* out = (float*)d_out;

    cudaFuncSetAttribute(attn_tc_kernel, cudaFuncAttributeMaxDynamicSharedMemorySize, ATTN_SMEM);

    ln_kernel<<<ROWS / 8, dim3(32, 8)>>>(msa, ln_s, ln_b);
    transpose_w<<<dim3(8, 8, 5), dim3(32, 8)>>>(wq, wk, wv, wg, wo);
    proj_kernel<<<dim3(ROWS / 128, 8), 256>>>(bg);
    attn_tc_kernel<<<L_DIM * H_DIM, 128, ATTN_SMEM>>>();
    outproj_kernel<<<dim3(ROWS / 128, 2), 256>>>(bo, out);
}